// round 4
// baseline (speedup 1.0000x reference)
#include <cuda_runtime.h>
#include <math.h>

#define T_DATA 200000
#define SUB_NO 20
#define T_NO   200
#define E_NO   400
#define I_NO   100
#define N_BASIS 20

// ---------------- scratch (device globals; no allocations allowed) ----------
__device__ float  g_syn_e [SUB_NO * T_DATA];
__device__ float  g_syn_i [SUB_NO * T_DATA];
__device__ float  g_syn_ns[SUB_NO * T_DATA];
__device__ float  g_syn_s [SUB_NO * T_DATA];
__device__ float  g_hist_ns[T_DATA];
__device__ float  g_hist_s [T_DATA];
__device__ float4 g_kern4[SUB_NO * T_NO];   // {e_ns, i_ns, e_s, i_s} per (s, j)
__device__ float  g_hk_ns[T_NO];
__device__ float  g_hk_s [T_NO];
__device__ int    g_e_asn[E_NO];
__device__ int    g_i_asn[I_NO];
__device__ int    g_parent[SUB_NO];

// ---------------- K1: filters, assignments, tree parents --------------------
__global__ void setup_kernel(const float* __restrict__ Wns,
                             const float* __restrict__ Tau,
                             const float* __restrict__ Delta,
                             const float* __restrict__ Wsyn_s,
                             const float* __restrict__ hist_s_w,
                             const float* __restrict__ hist_ns_w,
                             const float* __restrict__ C_syn_e,
                             const float* __restrict__ C_syn_i,
                             const int*   __restrict__ C_den,
                             float* __restrict__ out_filters)
{
    const float PI_F = 3.14159265358979323846f;
    int tid = threadIdx.x;

    for (int idx = tid; idx < SUB_NO * T_NO; idx += blockDim.x) {
        int s = idx / T_NO;
        int j = idx - s * T_NO;
        float t = (float)j;
        float tau_e = Tau[s*2+0] * Tau[s*2+0];
        float tau_i = Tau[s*2+1] * Tau[s*2+1];
        float te = fmaxf(t - Delta[s*2+0], 0.0f) / tau_e;
        float ti = fmaxf(t - Delta[s*2+1], 0.0f) / tau_i;
        float we0 = Wns[s*2+0], wi0 = Wns[s*2+1];
        float ke =  te * expf(-te) * we0 * we0;
        float ki = -ti * expf(-ti) * wi0 * wi0;

        float raw = 5.0f * logf(t + 1.0f);
        float se = 0.0f, si = 0.0f;
        #pragma unroll
        for (int b = 0; b < N_BASIS; b++) {
            float phi = 1.57079632679489662f * (float)b;
            float v = 0.0f;
            if (raw >= phi - PI_F && raw <= phi + PI_F)
                v = 0.5f * cosf(raw - phi) + 0.5f;
            float wse = Wsyn_s[(s*N_BASIS + b)*2 + 0];
            float wsi = Wsyn_s[(s*N_BASIS + b)*2 + 1];
            se += wse * wse * v;
            si += wsi * wsi * v;
        }
        si = -si;

        g_kern4[idx] = make_float4(ke, ki, se, si);
        out_filters[0*SUB_NO*T_NO + idx] = ke;
        out_filters[1*SUB_NO*T_NO + idx] = ki;
        out_filters[2*SUB_NO*T_NO + idx] = se;
        out_filters[3*SUB_NO*T_NO + idx] = si;
    }

    for (int j = tid; j < T_NO; j += blockDim.x) {
        float raw = 5.0f * logf((float)j + 1.0f);
        float hs = 0.0f, hns = 0.0f;
        #pragma unroll
        for (int b = 0; b < N_BASIS; b++) {
            float phi = 1.57079632679489662f * (float)b;
            float v = 0.0f;
            if (raw >= phi - PI_F && raw <= phi + PI_F)
                v = 0.5f * cosf(raw - phi) + 0.5f;
            hs  += hist_s_w[b]  * v;
            hns += hist_ns_w[b] * v;
        }
        g_hk_s[j]  = hs;
        g_hk_ns[j] = hns;
        out_filters[4*SUB_NO*T_NO + j]        = hns;  // row 80
        out_filters[4*SUB_NO*T_NO + T_NO + j] = hs;   // row 81
    }

    for (int e = tid; e < E_NO; e += blockDim.x) {
        int a = 0;
        for (int s = 0; s < SUB_NO; s++)
            if (C_syn_e[s*E_NO + e] != 0.0f) a = s;
        g_e_asn[e] = a;
    }
    for (int i2 = tid; i2 < I_NO; i2 += blockDim.x) {
        int a = 0;
        for (int s = 0; s < SUB_NO; s++)
            if (C_syn_i[s*I_NO + i2] != 0.0f) a = s;
        g_i_asn[i2] = a;
    }
    for (int c = tid; c < SUB_NO; c += blockDim.x) {
        int p = 0;
        for (int s = 0; s < SUB_NO; s++)
            if (C_den[s*SUB_NO + c] != 0) p = s;
        g_parent[c] = p;
    }
}

// ---------------- K2: spike binning  syn = S @ C.T (one-hot) ----------------
#define BT 16
__global__ void bin_kernel(const float* __restrict__ S_e,
                           const float* __restrict__ S_i)
{
    __shared__ float be[BT * SUB_NO];
    __shared__ float bi[BT * SUB_NO];
    const int tid = threadIdx.x;
    const int t0  = blockIdx.x * BT;

    for (int i = tid; i < BT * SUB_NO; i += blockDim.x) { be[i] = 0.0f; bi[i] = 0.0f; }
    __syncthreads();

    for (int idx = tid; idx < BT * E_NO; idx += blockDim.x) {
        int tl = idx / E_NO;
        int e  = idx - tl * E_NO;
        int t  = t0 + tl;
        if (t < T_DATA) {
            float v = S_e[(size_t)t * E_NO + e];
            if (v != 0.0f) atomicAdd(&be[tl * SUB_NO + g_e_asn[e]], v);
        }
    }
    for (int idx = tid; idx < BT * I_NO; idx += blockDim.x) {
        int tl = idx / I_NO;
        int i2 = idx - tl * I_NO;
        int t  = t0 + tl;
        if (t < T_DATA) {
            float v = S_i[(size_t)t * I_NO + i2];
            if (v != 0.0f) atomicAdd(&bi[tl * SUB_NO + g_i_asn[i2]], v);
        }
    }
    __syncthreads();

    for (int idx = tid; idx < BT * SUB_NO; idx += blockDim.x) {
        int s  = idx / BT;
        int tl = idx - s * BT;
        int t  = t0 + tl;
        if (t < T_DATA) {
            g_syn_e[(size_t)s * T_DATA + t] = be[tl * SUB_NO + s];
            g_syn_i[(size_t)s * T_DATA + t] = bi[tl * SUB_NO + s];
        }
    }
}

// ---------------- K3: grouped causal convolution ----------------------------
#define CT  1024     // timesteps per block
#define CTH 128      // threads per block
#define CR  8        // timesteps per thread (contiguous)
// skewed smem index: kills the 8-way bank conflict of the 32B lane stride
__device__ __forceinline__ int sk(int i) { return i + (i >> 3); }
#define XSZ  (CT + T_NO)
#define XPADSZ (XSZ + (XSZ >> 3) + 2)

__global__ __launch_bounds__(CTH) void conv_kernel()
{
    const int s  = blockIdx.y;
    const int t0 = blockIdx.x * CT;
    __shared__ float  xe[XPADSZ];
    __shared__ float  xi[XPADSZ];
    __shared__ float4 kk[T_NO];
    const int tid = threadIdx.x;

    const float* pe = g_syn_e + (size_t)s * T_DATA;
    const float* pi = g_syn_i + (size_t)s * T_DATA;
    for (int i = tid; i < XSZ; i += CTH) {
        int t = t0 - T_NO + i;          // xe[i] <-> global t0 - T_NO + i
        bool ok = (t >= 0) && (t < T_DATA);
        xe[sk(i)] = ok ? pe[t] : 0.0f;
        xi[sk(i)] = ok ? pi[t] : 0.0f;
    }
    for (int j = tid; j < T_NO; j += CTH) kk[j] = g_kern4[s * T_NO + j];
    __syncthreads();

    const int b = tid * CR;
    float accn[CR], accs[CR], we[CR], wi[CR];
    #pragma unroll
    for (int r = 0; r < CR; r++) {
        accn[r] = 0.0f; accs[r] = 0.0f;
        we[r] = xe[sk(b + r + T_NO)];   // window for j = 0
        wi[r] = xi[sk(b + r + T_NO)];
    }

    #pragma unroll 8
    for (int j = 0; j < T_NO; j++) {
        float4 k = kk[j];
        #pragma unroll
        for (int r = 0; r < CR; r++) {
            accn[r] = fmaf(k.x, we[r], accn[r]);
            accn[r] = fmaf(k.y, wi[r], accn[r]);
            accs[r] = fmaf(k.z, we[r], accs[r]);
            accs[r] = fmaf(k.w, wi[r], accs[r]);
        }
        #pragma unroll
        for (int r = CR - 1; r > 0; r--) { we[r] = we[r-1]; wi[r] = wi[r-1]; }
        int i2 = b + T_NO - 1 - j;      // >= 0 always
        we[0] = xe[sk(i2)];
        wi[0] = xi[sk(i2)];
    }

    float* on = g_syn_ns + (size_t)s * T_DATA + t0 + b;
    float* os = g_syn_s  + (size_t)s * T_DATA + t0 + b;
    #pragma unroll
    for (int r = 0; r < CR; r++) {
        if (t0 + b + r < T_DATA) { on[r] = accn[r]; os[r] = accs[r]; }
    }
}

// ---------------- K3b: spike-history conv of Z (one-step delayed) -----------
#define HXSZ (CT + T_NO + 1)
#define HXPAD (HXSZ + (HXSZ >> 3) + 2)
__global__ __launch_bounds__(CTH) void hist_kernel(const float* __restrict__ Z)
{
    const int t0 = blockIdx.x * CT;
    __shared__ float  xz[HXPAD];
    __shared__ float2 hk[T_NO];
    const int tid = threadIdx.x;

    for (int i = tid; i < HXSZ; i += CTH) {
        int t = t0 - T_NO - 1 + i;      // xz[i] <-> global t0 - T_NO - 1 + i
        xz[sk(i)] = (t >= 0 && t < T_DATA) ? Z[t] : 0.0f;
    }
    for (int j = tid; j < T_NO; j += CTH) hk[j] = make_float2(g_hk_ns[j], g_hk_s[j]);
    __syncthreads();

    const int b = tid * CR;
    float an[CR], as2[CR], w[CR];
    #pragma unroll
    for (int r = 0; r < CR; r++) {
        an[r] = 0.0f; as2[r] = 0.0f;
        // need Z[t - 1 - j]; smem index = (local t) + T_NO - j, j = 0:
        w[r] = xz[sk(b + r + T_NO)];
    }
    #pragma unroll 8
    for (int j = 0; j < T_NO; j++) {
        float2 k = hk[j];
        #pragma unroll
        for (int r = 0; r < CR; r++) {
            an[r]  = fmaf(k.x, w[r], an[r]);
            as2[r] = fmaf(k.y, w[r], as2[r]);
        }
        #pragma unroll
        for (int r = CR - 1; r > 0; r--) w[r] = w[r-1];
        w[0] = xz[sk(b + T_NO - 1 - j)];
    }
    #pragma unroll
    for (int r = 0; r < CR; r++) {
        int t = t0 + b + r;
        if (t < T_DATA) { g_hist_ns[t] = an[r]; g_hist_s[t] = as2[r]; }
    }
}

// ---------------- K4: leaf-to-root tree (pointwise in t) + outputs ----------
#define TTH 128
__global__ __launch_bounds__(TTH) void tree_kernel(
    const float* __restrict__ Theta_ns, const float* __restrict__ Theta_s,
    const float* __restrict__ W_sub_ns, const float* __restrict__ W_sub_s,
    const float* __restrict__ V_o, float* __restrict__ out)
{
    __shared__ float as_[SUB_NO][TTH];
    __shared__ float an_[SUB_NO][TTH];
    __shared__ float ws2[SUB_NO], wn2[SUB_NO], ths[SUB_NO], thn[SUB_NO];
    __shared__ int   par[SUB_NO];
    const int tid = threadIdx.x;

    if (tid < SUB_NO) {
        float w = W_sub_s[tid];  ws2[tid] = w * w;
        w = W_sub_ns[tid];       wn2[tid] = w * w;
        ths[tid] = Theta_s[tid];
        thn[tid] = Theta_ns[tid];
        par[tid] = g_parent[tid];
    }
    __syncthreads();

    const int t  = blockIdx.x * TTH + tid;
    const int tr = (t < T_DATA) ? t : (T_DATA - 1);

    #pragma unroll
    for (int s2 = 0; s2 < SUB_NO; s2++) {
        as_[s2][tid] = g_syn_s [(size_t)s2 * T_DATA + tr] + ths[s2];
        an_[s2][tid] = g_syn_ns[(size_t)s2 * T_DATA + tr] + thn[s2];
    }

    #pragma unroll
    for (int idx = SUB_NO - 1; idx >= 1; idx--) {
        int p = par[idx];
        float vs = tanhf(as_[idx][tid]);
        float vn = tanhf(an_[idx][tid]);
        as_[p][tid] += vs * ws2[idx];
        an_[p][tid] += vn * wn2[idx];
    }

    float s0 = 1.0f / (1.0f + expf(-(g_hist_s[tr] + as_[0][tid])));
    float n0 = tanhf(g_hist_ns[tr] + an_[0][tid]);
    if (t < T_DATA) {
        out[t]          = n0 * wn2[0] + V_o[0];  // final_V
        out[T_DATA + t] = s0;                    // final_Z
    }
}

// ---------------- launch ----------------------------------------------------
extern "C" void kernel_launch(void* const* d_in, const int* in_sizes, int n_in,
                              void* d_out, int out_size)
{
    const float* S_e      = (const float*)d_in[0];
    const float* S_i      = (const float*)d_in[1];
    const float* Z        = (const float*)d_in[2];
    const int*   C_den    = (const int*)  d_in[3];
    const float* C_syn_e  = (const float*)d_in[4];
    const float* C_syn_i  = (const float*)d_in[5];
    const float* W_syn_ns = (const float*)d_in[6];
    const float* Tau      = (const float*)d_in[7];
    const float* Delta    = (const float*)d_in[8];
    const float* W_syn_s  = (const float*)d_in[9];
    const float* W_sub_ns = (const float*)d_in[10];
    const float* W_sub_s  = (const float*)d_in[11];
    const float* V_o      = (const float*)d_in[12];
    const float* Theta_ns = (const float*)d_in[13];
    const float* Theta_s  = (const float*)d_in[14];
    const float* hist_s_w = (const float*)d_in[15];
    const float* hist_ns_w= (const float*)d_in[16];

    float* out = (float*)d_out;
    float* out_filters = out + 2 * T_DATA;   // final_V | final_Z | filters(82x200)

    setup_kernel<<<1, 256>>>(W_syn_ns, Tau, Delta, W_syn_s, hist_s_w, hist_ns_w,
                             C_syn_e, C_syn_i, C_den, out_filters);

    bin_kernel<<<(T_DATA + BT - 1) / BT, 256>>>(S_e, S_i);

    dim3 cgrid((T_DATA + CT - 1) / CT, SUB_NO);
    conv_kernel<<<cgrid, CTH>>>();

    hist_kernel<<<(T_DATA + CT - 1) / CT, CTH>>>(Z);

    tree_kernel<<<(T_DATA + TTH - 1) / TTH, TTH>>>(Theta_ns, Theta_s,
                                                   W_sub_ns, W_sub_s, V_o, out);
}

// round 6
// speedup vs baseline: 1.2739x; 1.2739x over previous
#include <cuda_runtime.h>
#include <math.h>

#define T_DATA 200000
#define SUB_NO 20
#define T_NO   200
#define E_NO   400
#define I_NO   100
#define N_BASIS 20

typedef unsigned long long ull;

// ---------------- packed f32x2 helpers --------------------------------------
__device__ __forceinline__ ull fma2(ull a, ull b, ull c) {
    ull d;
    asm("fma.rn.f32x2 %0, %1, %2, %3;" : "=l"(d) : "l"(a), "l"(b), "l"(c));
    return d;
}
__device__ __forceinline__ ull pk2(float lo, float hi) {
    ull r;
    asm("mov.b64 %0, {%1, %2};" : "=l"(r) : "f"(lo), "f"(hi));
    return r;
}
__device__ __forceinline__ float tanh_ap(float x) {
    float y;
    asm("tanh.approx.f32 %0, %1;" : "=f"(y) : "f"(x));
    return y;
}

// ---------------- scratch (device globals; no allocations allowed) ----------
__device__ float  g_syn_e [SUB_NO * T_DATA];
__device__ float  g_syn_i [SUB_NO * T_DATA];
__device__ float  g_syn_ns[SUB_NO * T_DATA];
__device__ float  g_syn_s [SUB_NO * T_DATA];
__device__ float  g_hist_ns[T_DATA];
__device__ float  g_hist_s [T_DATA];
__device__ ull    g_kd[SUB_NO * T_NO * 4];  // duplicated (k,k) pairs {e_ns,i_ns,e_s,i_s}
__device__ ull    g_hd[T_NO * 2];           // duplicated hist kernels {ns, s}
__device__ int    g_e_asn[E_NO];
__device__ int    g_i_asn[I_NO];
__device__ int    g_parent[SUB_NO];

// ---------------- K1: filters, assignments, tree parents --------------------
__global__ void setup_kernel(const float* __restrict__ Wns,
                             const float* __restrict__ Tau,
                             const float* __restrict__ Delta,
                             const float* __restrict__ Wsyn_s,
                             const float* __restrict__ hist_s_w,
                             const float* __restrict__ hist_ns_w,
                             const float* __restrict__ C_syn_e,
                             const float* __restrict__ C_syn_i,
                             const int*   __restrict__ C_den,
                             float* __restrict__ out_filters)
{
    const float PI_F = 3.14159265358979323846f;
    int tid = threadIdx.x;

    for (int idx = tid; idx < SUB_NO * T_NO; idx += blockDim.x) {
        int s = idx / T_NO;
        int j = idx - s * T_NO;
        float t = (float)j;
        float tau_e = Tau[s*2+0] * Tau[s*2+0];
        float tau_i = Tau[s*2+1] * Tau[s*2+1];
        float te = fmaxf(t - Delta[s*2+0], 0.0f) / tau_e;
        float ti = fmaxf(t - Delta[s*2+1], 0.0f) / tau_i;
        float we0 = Wns[s*2+0], wi0 = Wns[s*2+1];
        float ke =  te * expf(-te) * we0 * we0;
        float ki = -ti * expf(-ti) * wi0 * wi0;

        float raw = 5.0f * logf(t + 1.0f);
        float se = 0.0f, si = 0.0f;
        #pragma unroll
        for (int b = 0; b < N_BASIS; b++) {
            float phi = 1.57079632679489662f * (float)b;
            float v = 0.0f;
            if (raw >= phi - PI_F && raw <= phi + PI_F)
                v = 0.5f * cosf(raw - phi) + 0.5f;
            float wse = Wsyn_s[(s*N_BASIS + b)*2 + 0];
            float wsi = Wsyn_s[(s*N_BASIS + b)*2 + 1];
            se += wse * wse * v;
            si += wsi * wsi * v;
        }
        si = -si;

        g_kd[idx*4 + 0] = pk2(ke, ke);
        g_kd[idx*4 + 1] = pk2(ki, ki);
        g_kd[idx*4 + 2] = pk2(se, se);
        g_kd[idx*4 + 3] = pk2(si, si);
        out_filters[0*SUB_NO*T_NO + idx] = ke;
        out_filters[1*SUB_NO*T_NO + idx] = ki;
        out_filters[2*SUB_NO*T_NO + idx] = se;
        out_filters[3*SUB_NO*T_NO + idx] = si;
    }

    for (int j = tid; j < T_NO; j += blockDim.x) {
        float raw = 5.0f * logf((float)j + 1.0f);
        float hs = 0.0f, hns = 0.0f;
        #pragma unroll
        for (int b = 0; b < N_BASIS; b++) {
            float phi = 1.57079632679489662f * (float)b;
            float v = 0.0f;
            if (raw >= phi - PI_F && raw <= phi + PI_F)
                v = 0.5f * cosf(raw - phi) + 0.5f;
            hs  += hist_s_w[b]  * v;
            hns += hist_ns_w[b] * v;
        }
        g_hd[j*2 + 0] = pk2(hns, hns);
        g_hd[j*2 + 1] = pk2(hs, hs);
        out_filters[4*SUB_NO*T_NO + j]        = hns;  // row 80
        out_filters[4*SUB_NO*T_NO + T_NO + j] = hs;   // row 81
    }

    for (int e = tid; e < E_NO; e += blockDim.x) {
        int a = 0;
        for (int s = 0; s < SUB_NO; s++)
            if (C_syn_e[s*E_NO + e] != 0.0f) a = s;
        g_e_asn[e] = a;
    }
    for (int i2 = tid; i2 < I_NO; i2 += blockDim.x) {
        int a = 0;
        for (int s = 0; s < SUB_NO; s++)
            if (C_syn_i[s*I_NO + i2] != 0.0f) a = s;
        g_i_asn[i2] = a;
    }
    for (int c = tid; c < SUB_NO; c += blockDim.x) {
        int p = 0;
        for (int s = 0; s < SUB_NO; s++)
            if (C_den[s*SUB_NO + c] != 0) p = s;
        g_parent[c] = p;
    }
}

// ---------------- K2: spike binning  syn = S @ C.T (one-hot), float4 --------
#define BT   32
#define BTH  256
__global__ __launch_bounds__(BTH) void bin_kernel(const float4* __restrict__ Se4,
                                                  const float4* __restrict__ Si4)
{
    __shared__ float be[BT * SUB_NO];
    __shared__ float bi[BT * SUB_NO];
    __shared__ int   ea[E_NO];
    __shared__ int   ia[I_NO];
    const int tid = threadIdx.x;
    const int t0  = blockIdx.x * BT;

    for (int i = tid; i < BT * SUB_NO; i += BTH) { be[i] = 0.0f; bi[i] = 0.0f; }
    for (int i = tid; i < E_NO; i += BTH) ea[i] = g_e_asn[i];
    for (int i = tid; i < I_NO; i += BTH) ia[i] = g_i_asn[i];
    __syncthreads();

    // excitatory: BT rows x 100 float4
    for (int idx = tid; idx < BT * (E_NO/4); idx += BTH) {
        int r = idx / (E_NO/4);
        int c = idx - r * (E_NO/4);
        int t = t0 + r;
        if (t < T_DATA) {
            float4 v = Se4[(size_t)t * (E_NO/4) + c];
            int e0 = c * 4;
            if (v.x != 0.0f) atomicAdd(&be[r * SUB_NO + ea[e0+0]], v.x);
            if (v.y != 0.0f) atomicAdd(&be[r * SUB_NO + ea[e0+1]], v.y);
            if (v.z != 0.0f) atomicAdd(&be[r * SUB_NO + ea[e0+2]], v.z);
            if (v.w != 0.0f) atomicAdd(&be[r * SUB_NO + ea[e0+3]], v.w);
        }
    }
    // inhibitory: BT rows x 25 float4
    for (int idx = tid; idx < BT * (I_NO/4); idx += BTH) {
        int r = idx / (I_NO/4);
        int c = idx - r * (I_NO/4);
        int t = t0 + r;
        if (t < T_DATA) {
            float4 v = Si4[(size_t)t * (I_NO/4) + c];
            int i0 = c * 4;
            if (v.x != 0.0f) atomicAdd(&bi[r * SUB_NO + ia[i0+0]], v.x);
            if (v.y != 0.0f) atomicAdd(&bi[r * SUB_NO + ia[i0+1]], v.y);
            if (v.z != 0.0f) atomicAdd(&bi[r * SUB_NO + ia[i0+2]], v.z);
            if (v.w != 0.0f) atomicAdd(&bi[r * SUB_NO + ia[i0+3]], v.w);
        }
    }
    __syncthreads();

    for (int idx = tid; idx < BT * SUB_NO; idx += BTH) {
        int s  = idx / BT;
        int tl = idx - s * BT;
        int t  = t0 + tl;
        if (t < T_DATA) {
            g_syn_e[(size_t)s * T_DATA + t] = be[tl * SUB_NO + s];
            g_syn_i[(size_t)s * T_DATA + t] = bi[tl * SUB_NO + s];
        }
    }
}

// ---------------- K3: grouped causal conv (packed f32x2) + hist slice -------
// Packing: accumulator pair = adjacent output timesteps (t, t+1).
// Even taps j use even-aligned window pairs (WE); odd taps use odd-aligned
// pairs (WO) refilled from a 1-float-shifted smem copy so LDS.64 stays aligned.
// Window shift per 2 taps = whole-pair rotation (renamed away by unroll).
#define CT  1024     // timesteps per block
#define CTH 128      // threads per block
#define XSZ (CT + T_NO)   // 1224

__global__ __launch_bounds__(CTH) void conv_kernel(const float* __restrict__ Z)
{
    const int s  = blockIdx.y;
    const int t0 = blockIdx.x * CT;
    __shared__ __align__(16) float xe [XSZ];
    __shared__ __align__(16) float xes[XSZ];
    __shared__ __align__(16) float xi [XSZ];
    __shared__ __align__(16) float xis[XSZ];
    __shared__ ull kd[T_NO * 4];
    const int tid = threadIdx.x;
    const int b   = tid * 8;

    if (s < SUB_NO) {
        const float* pe = g_syn_e + (size_t)s * T_DATA;
        const float* pi = g_syn_i + (size_t)s * T_DATA;
        for (int i = tid; i < XSZ; i += CTH) {
            int t  = t0 - T_NO + i;
            int t1 = t + 1;
            bool ok0 = (t  >= 0) && (t  < T_DATA);
            bool ok1 = (t1 >= 0) && (t1 < T_DATA);
            xe [i] = ok0 ? pe[t]  : 0.0f;
            xi [i] = ok0 ? pi[t]  : 0.0f;
            xes[i] = ok1 ? pe[t1] : 0.0f;
            xis[i] = ok1 ? pi[t1] : 0.0f;
        }
        for (int i = tid; i < T_NO * 4; i += CTH)
            kd[i] = g_kd[(size_t)s * T_NO * 4 + i];
        __syncthreads();

        const ull* xeP = (const ull*)(xe  + b + 200);  // even pairs, tap j=2jj: [-jj+p]
        const ull* xoP = (const ull*)(xes + b + 198);  // odd  pairs, tap j=2jj+1
        const ull* xiP = (const ull*)(xi  + b + 200);
        const ull* xjP = (const ull*)(xis + b + 198);

        ull WEe[4], WOe[4], WEi[4], WOi[4], an[4], as2[4];
        #pragma unroll
        for (int p = 0; p < 4; p++) {
            WEe[p] = xeP[p]; WOe[p] = xoP[p];
            WEi[p] = xiP[p]; WOi[p] = xjP[p];
            an[p] = 0ULL; as2[p] = 0ULL;
        }

        auto phases = [&](int jj) {
            ull k0e = kd[(2*jj)*4+0], k0i = kd[(2*jj)*4+1];
            ull k0s = kd[(2*jj)*4+2], k0t = kd[(2*jj)*4+3];
            #pragma unroll
            for (int p = 0; p < 4; p++) {
                an [p] = fma2(k0e, WEe[p], an [p]);
                an [p] = fma2(k0i, WEi[p], an [p]);
                as2[p] = fma2(k0s, WEe[p], as2[p]);
                as2[p] = fma2(k0t, WEi[p], as2[p]);
            }
            ull k1e = kd[(2*jj+1)*4+0], k1i = kd[(2*jj+1)*4+1];
            ull k1s = kd[(2*jj+1)*4+2], k1t = kd[(2*jj+1)*4+3];
            #pragma unroll
            for (int p = 0; p < 4; p++) {
                an [p] = fma2(k1e, WOe[p], an [p]);
                an [p] = fma2(k1i, WOi[p], an [p]);
                as2[p] = fma2(k1s, WOe[p], as2[p]);
                as2[p] = fma2(k1t, WOi[p], as2[p]);
            }
        };

        phases(0);
        #pragma unroll 4
        for (int jj = 1; jj < T_NO/2; jj++) {
            #pragma unroll
            for (int p = 3; p > 0; p--) {
                WEe[p] = WEe[p-1]; WOe[p] = WOe[p-1];
                WEi[p] = WEi[p-1]; WOi[p] = WOi[p-1];
            }
            WEe[0] = xeP[-jj]; WOe[0] = xoP[-jj];
            WEi[0] = xiP[-jj]; WOi[0] = xjP[-jj];
            phases(jj);
        }

        float* on = g_syn_ns + (size_t)s * T_DATA + t0 + b;
        float* os = g_syn_s  + (size_t)s * T_DATA + t0 + b;
        #pragma unroll
        for (int p = 0; p < 4; p++) {
            if (t0 + b + 2*p < T_DATA) {
                *(ull*)(on + 2*p) = an[p];
                *(ull*)(os + 2*p) = as2[p];
            }
        }
    } else {
        // ---- spike-history slice: g_hist[t] = sum_j k[j] * Z[t-1-j] ----
        for (int i = tid; i < XSZ; i += CTH) {
            int t  = t0 - T_NO + i - 1;     // x'[local i] = Z[t]
            int t1 = t + 1;
            xe [i] = (t  >= 0 && t  < T_DATA) ? Z[t]  : 0.0f;
            xes[i] = (t1 >= 0 && t1 < T_DATA) ? Z[t1] : 0.0f;
        }
        for (int i = tid; i < T_NO * 2; i += CTH) kd[i] = g_hd[i];
        __syncthreads();

        const ull* xeP = (const ull*)(xe  + b + 200);
        const ull* xoP = (const ull*)(xes + b + 198);
        ull WE[4], WO[4], hn[4], hs[4];
        #pragma unroll
        for (int p = 0; p < 4; p++) {
            WE[p] = xeP[p]; WO[p] = xoP[p];
            hn[p] = 0ULL; hs[p] = 0ULL;
        }
        auto phases = [&](int jj) {
            ull k0n = kd[(2*jj)*2+0], k0s = kd[(2*jj)*2+1];
            #pragma unroll
            for (int p = 0; p < 4; p++) {
                hn[p] = fma2(k0n, WE[p], hn[p]);
                hs[p] = fma2(k0s, WE[p], hs[p]);
            }
            ull k1n = kd[(2*jj+1)*2+0], k1s = kd[(2*jj+1)*2+1];
            #pragma unroll
            for (int p = 0; p < 4; p++) {
                hn[p] = fma2(k1n, WO[p], hn[p]);
                hs[p] = fma2(k1s, WO[p], hs[p]);
            }
        };
        phases(0);
        #pragma unroll 4
        for (int jj = 1; jj < T_NO/2; jj++) {
            #pragma unroll
            for (int p = 3; p > 0; p--) { WE[p] = WE[p-1]; WO[p] = WO[p-1]; }
            WE[0] = xeP[-jj]; WO[0] = xoP[-jj];
            phases(jj);
        }
        #pragma unroll
        for (int p = 0; p < 4; p++) {
            int t = t0 + b + 2*p;
            if (t < T_DATA) {
                *(ull*)(g_hist_ns + t) = hn[p];
                *(ull*)(g_hist_s  + t) = hs[p];
            }
        }
    }
}

// ---------------- K4: leaf-to-root tree (pointwise in t) + outputs ----------
#define TTH 128
__global__ __launch_bounds__(TTH) void tree_kernel(
    const float* __restrict__ Theta_ns, const float* __restrict__ Theta_s,
    const float* __restrict__ W_sub_ns, const float* __restrict__ W_sub_s,
    const float* __restrict__ V_o, float* __restrict__ out)
{
    __shared__ float as_[SUB_NO][TTH];
    __shared__ float an_[SUB_NO][TTH];
    __shared__ float ws2[SUB_NO], wn2[SUB_NO], ths[SUB_NO], thn[SUB_NO];
    __shared__ int   par[SUB_NO];
    const int tid = threadIdx.x;

    if (tid < SUB_NO) {
        float w = W_sub_s[tid];  ws2[tid] = w * w;
        w = W_sub_ns[tid];       wn2[tid] = w * w;
        ths[tid] = Theta_s[tid];
        thn[tid] = Theta_ns[tid];
        par[tid] = g_parent[tid];
    }
    __syncthreads();

    const int t  = blockIdx.x * TTH + tid;
    const int tr = (t < T_DATA) ? t : (T_DATA - 1);

    #pragma unroll
    for (int s2 = 0; s2 < SUB_NO; s2++) {
        as_[s2][tid] = g_syn_s [(size_t)s2 * T_DATA + tr] + ths[s2];
        an_[s2][tid] = g_syn_ns[(size_t)s2 * T_DATA + tr] + thn[s2];
    }

    #pragma unroll
    for (int idx = SUB_NO - 1; idx >= 1; idx--) {
        int p = par[idx];
        float vs = tanh_ap(as_[idx][tid]);
        float vn = tanh_ap(an_[idx][tid]);
        as_[p][tid] += vs * ws2[idx];
        an_[p][tid] += vn * wn2[idx];
    }

    float s0 = 0.5f * tanh_ap(0.5f * (g_hist_s[tr] + as_[0][tid])) + 0.5f;
    float n0 = tanh_ap(g_hist_ns[tr] + an_[0][tid]);
    if (t < T_DATA) {
        out[t]          = n0 * wn2[0] + V_o[0];  // final_V
        out[T_DATA + t] = s0;                    // final_Z
    }
}

// ---------------- launch ----------------------------------------------------
extern "C" void kernel_launch(void* const* d_in, const int* in_sizes, int n_in,
                              void* d_out, int out_size)
{
    const float* S_e      = (const float*)d_in[0];
    const float* S_i      = (const float*)d_in[1];
    const float* Z        = (const float*)d_in[2];
    const int*   C_den    = (const int*)  d_in[3];
    const float* C_syn_e  = (const float*)d_in[4];
    const float* C_syn_i  = (const float*)d_in[5];
    const float* W_syn_ns = (const float*)d_in[6];
    const float* Tau      = (const float*)d_in[7];
    const float* Delta    = (const float*)d_in[8];
    const float* W_syn_s  = (const float*)d_in[9];
    const float* W_sub_ns = (const float*)d_in[10];
    const float* W_sub_s  = (const float*)d_in[11];
    const float* V_o      = (const float*)d_in[12];
    const float* Theta_ns = (const float*)d_in[13];
    const float* Theta_s  = (const float*)d_in[14];
    const float* hist_s_w = (const float*)d_in[15];
    const float* hist_ns_w= (const float*)d_in[16];

    float* out = (float*)d_out;
    float* out_filters = out + 2 * T_DATA;   // final_V | final_Z | filters(82x200)

    setup_kernel<<<1, 256>>>(W_syn_ns, Tau, Delta, W_syn_s, hist_s_w, hist_ns_w,
                             C_syn_e, C_syn_i, C_den, out_filters);

    bin_kernel<<<(T_DATA + BT - 1) / BT, BTH>>>((const float4*)S_e,
                                                (const float4*)S_i);

    dim3 cgrid((T_DATA + CT - 1) / CT, SUB_NO + 1);  // y==SUB_NO -> hist slice
    conv_kernel<<<cgrid, CTH>>>(Z);

    tree_kernel<<<(T_DATA + TTH - 1) / TTH, TTH>>>(Theta_ns, Theta_s,
                                                   W_sub_ns, W_sub_s, V_o, out);
}